// round 16
// baseline (speedup 1.0000x reference)
#include <cuda_runtime.h>
#include <cstdint>
#include <cstddef>

#define N_NODES 20000
#define N_EDGES 320000
#define EPB 32

#define LOG2_C       0.6931471805599453f
#define INV_SQRT3_C  0.5773502691896258f
#define INV_SQRT8_C  0.35355339059327373f
#define W_SCALE      0.125f
#define INV_MUL_C    0.125f
#define SC_A_C       0.02209708691207961f   // 1/sqrt(128) * 1/sqrt(16)
#define SC_B_C       0.04419417382415922f   // 1/sqrt(512)

#define ROWS_S 20032
#define ROWS_V 60032
#define TILES_S 313
#define TILES_V 938

// scratch (__device__ globals). Referenced ONLY from device code.
__device__ __align__(1024) float d_sv[(size_t)N_NODES * 256];
__device__ __align__(1024) float d_cat_s[(size_t)ROWS_S * 640];
__device__ __align__(1024) float d_cat_v[(size_t)ROWS_V * 640];
__device__ __align__(1024) float d_WcatT_s[64 * 640];
__device__ __align__(1024) float d_WcatT_v[64 * 640];

__device__ __forceinline__ unsigned smem_u32(const void* p) {
    return (unsigned)__cvta_generic_to_shared(p);
}
__device__ __forceinline__ float4 ld4s(const float* p) {
    return *reinterpret_cast<const float4*>(p);
}
__device__ __forceinline__ void cp_async16(unsigned saddr, const void* gaddr) {
    asm volatile("cp.async.cg.shared.global [%0], [%1], 16;" :: "r"(saddr), "l"(gaddr));
}
__device__ __forceinline__ void cp_commit() {
    asm volatile("cp.async.commit_group;" ::: "memory");
}
template<int NWAIT>
__device__ __forceinline__ void cp_wait() {
    asm volatile("cp.async.wait_group %0;" :: "n"(NWAIT) : "memory");
}

// ---- tf32 helpers ------------------------------------------------------
__device__ __forceinline__ unsigned f2tf32(float f) {
    unsigned r;
    asm("cvt.rna.tf32.f32 %0, %1;" : "=r"(r) : "f"(f));
    return r;
}
__device__ __forceinline__ void mma_tf32(float& c0, float& c1, float& c2, float& c3,
                                         unsigned a0, unsigned a1, unsigned a2, unsigned a3,
                                         unsigned b0, unsigned b1) {
    asm volatile(
        "mma.sync.aligned.m16n8k8.row.col.f32.tf32.tf32.f32 "
        "{%0,%1,%2,%3}, {%4,%5,%6,%7}, {%8,%9}, {%0,%1,%2,%3};"
        : "+f"(c0), "+f"(c1), "+f"(c2), "+f"(c3)
        : "r"(a0), "r"(a1), "r"(a2), "r"(a3), "r"(b0), "r"(b1));
}

// ---- log1p(t), t in [0,1]: degree-7 poly (err ~2e-7), MUFU-free ---------
__device__ __forceinline__ float log1p_poly(float t) {
    const float u = fmaf(2.f, t, -1.f);
    float p = 0.0000800429f;
    p = fmaf(p, u, -0.000272121f);
    p = fmaf(p, u,  0.000811464f);
    p = fmaf(p, u, -0.00305802f);
    p = fmaf(p, u,  0.01234897f);
    p = fmaf(p, u, -0.05556137f);
    p = fmaf(p, u,  0.33333319f);
    p = fmaf(p, u,  0.4054653f);
    return p;
}

// ---------------------------------------------------------------------------
__global__ void wfold_kernel(const float* __restrict__ W2s, const float* __restrict__ Wsc_s,
                             const float* __restrict__ W2v, const float* __restrict__ Wsc_v)
{
    const int i = blockIdx.x * blockDim.x + threadIdx.x;
    if (i >= 40960) return;
    const int n = i / 640, k = i - n * 640;
    const float vs = (k < 128) ? W2s[k * 64 + n] * SC_A_C : Wsc_s[(k - 128) * 64 + n] * SC_B_C;
    const float vv = (k < 128) ? W2v[k * 64 + n] * SC_A_C : Wsc_v[(k - 128) * 64 + n] * SC_B_C;
    d_WcatT_s[i] = __uint_as_float(f2tf32(vs));
    d_WcatT_v[i] = __uint_as_float(f2tf32(vv));
}

// ---------------------------------------------------------------------------
// node prep (unchanged)
// ---------------------------------------------------------------------------
__global__ void __launch_bounds__(256)
nodeprep_kernel(const float* __restrict__ node_feat,
                const float* __restrict__ node_attr,
                const float* __restrict__ W1s,
                const float* __restrict__ W1v)
{
    __shared__ float sW1s[4096];
    __shared__ float sW1v[4096];
    __shared__ float sNF[4][256];
    __shared__ float4 sAT[4][2];

    const int tid = threadIdx.x;
    for (int i = tid; i < 4096; i += 256) { sW1s[i] = W1s[i]; sW1v[i] = W1v[i]; }
    __syncthreads();

    const int ngroups = N_NODES / 4;
    for (int g = blockIdx.x; g < ngroups; g += gridDim.x) {
        const int n0 = g * 4;
        __syncthreads();
        for (int i = tid; i < 1024; i += 256) {
            const int nl = i >> 8, j = i & 255;
            sNF[nl][j] = node_feat[(size_t)(n0 + nl) * 256 + j];
        }
        if (tid < 8) {
            const int nl = tid >> 1, j = tid & 1;
            sAT[nl][j] = __ldg(reinterpret_cast<const float4*>(node_attr + (size_t)(n0 + nl) * 8) + j);
        }
        __syncthreads();

        {
            const int nl = tid >> 6, w = tid & 63;
            const int n = n0 + nl;
            float sacc = 0.f, v0a = 0.f, v1a = 0.f, v2a = 0.f;
#pragma unroll
            for (int u = 0; u < 64; ++u) {
                const float ws = sW1s[u * 64 + w];
                const float wvv = sW1v[u * 64 + w];
                sacc = fmaf(sNF[nl][u], ws, sacc);
                v0a  = fmaf(sNF[nl][64 + 3 * u + 0], wvv, v0a);
                v1a  = fmaf(sNF[nl][64 + 3 * u + 1], wvv, v1a);
                v2a  = fmaf(sNF[nl][64 + 3 * u + 2], wvv, v2a);
            }
            float* o = d_sv + (size_t)n * 256;
            o[w] = sacc * INV_MUL_C;
            o[64 + 3 * w + 0] = v0a * INV_MUL_C;
            o[64 + 3 * w + 1] = v1a * INV_MUL_C;
            o[64 + 3 * w + 2] = v2a * INV_MUL_C;
        }

        if (tid < 128) {
            const int nl = tid >> 5, u = tid & 31;
            reinterpret_cast<float4*>(d_cat_s + (size_t)(n0 + nl) * 640)[u] =
                make_float4(0.f, 0.f, 0.f, 0.f);
        }
        for (int i = tid; i < 384; i += 256) {
            const int rr = i >> 5, u = i & 31;
            const int nl = rr / 3, c = rr - 3 * nl;
            reinterpret_cast<float4*>(d_cat_v + ((size_t)(n0 + nl) * 3 + c) * 640)[u] =
                make_float4(0.f, 0.f, 0.f, 0.f);
        }

        for (int i = tid; i < 512; i += 256) {
            const int nl = i >> 7, p4 = i & 127;
            const float a = sNF[nl][p4 >> 1];
            const float4 at = sAT[nl][p4 & 1];
            reinterpret_cast<float4*>(d_cat_s + (size_t)(n0 + nl) * 640 + 128)[p4] =
                make_float4(a * at.x, a * at.y, a * at.z, a * at.w);
        }
        for (int i = tid; i < 1536; i += 256) {
            const int nl = i / 384;
            const int r  = i - nl * 384;
            const int c  = r >> 7, p4 = r & 127;
            const float a = sNF[nl][64 + 3 * (p4 >> 1) + c];
            const float4 at = sAT[nl][p4 & 1];
            reinterpret_cast<float4*>(d_cat_v + ((size_t)(n0 + nl) * 3 + c) * 640 + 128)[p4] =
                make_float4(a * at.x, a * at.y, a * at.z, a * at.w);
        }
    }
}

// ---------------------------------------------------------------------------
// edge kernel v7: EPB=32, 512 threads, 1 CTA/SM. Contiguous tiles (no sort).
// Warp w: mt = w>>3 (edge half), colwarp = w&7 -> cols [32*colwarp, +32),
// region = colwarp>>1. Per-edge work identical to v5; fixed per-iteration
// overhead (barriers, waits, bundle/reduce issue) amortized over 2x edges.
// smem (floats):
//   sOut [0,33024)        2*32*516
//   sGat [33024,49664)    2*32*260
//   sH   [49664,51840)    32*68
//   sWfc1[51840,52352)
//   sBas [52352,52864)    2*32*8
//   sShs [52864,53120)    2*32*4
//   sIdx [53120,53248)    2*32*2 ints
// total 53248 floats = 212992 B -> 1 CTA/SM
// ---------------------------------------------------------------------------
#define SOUT_STRIDE 516
#define GAT_STRIDE 260
#define EDGE_SMEM (53248 * 4)

__global__ void __launch_bounds__(512, 1)
edge_kernel(const float* __restrict__ edge_sh,
            const float* __restrict__ edge_basis,
            const float* __restrict__ Wfc1,
            const float* __restrict__ Wfc2,
            const int*   __restrict__ edge_idx)
{
    extern __shared__ float esm[];
    float*    sOut  = esm;
    float*    sGat  = esm + 33024;
    float*    sH    = esm + 49664;
    unsigned* sHu   = reinterpret_cast<unsigned*>(sH);
    float*    sWfc1 = esm + 51840;
    float*    sBas  = esm + 52352;
    float*    sShs  = esm + 52864;
    int*      sIdx  = (int*)(esm + 53120);

    const int tid  = threadIdx.x;
    const int lane = tid & 31, warp = tid >> 5;
    const int g    = lane >> 2;
    const int ctig = lane & 3;
    const int colwarp = warp & 7;
    const int mt   = warp >> 3;          // which 16-edge half of the tile
    const int n0   = colwarp * 32;
    const int region = colwarp >> 1;
    const int qb   = mt * 16;            // edge-row base for this warp

    unsigned bfrag[8][4][2];
#pragma unroll
    for (int ks = 0; ks < 8; ++ks)
#pragma unroll
        for (int nb = 0; nb < 4; ++nb) {
            const int nn = n0 + nb * 8 + g;
            bfrag[ks][nb][0] = f2tf32(Wfc2[(ks * 8 + ctig    ) * 256 + nn] * W_SCALE);
            bfrag[ks][nb][1] = f2tf32(Wfc2[(ks * 8 + ctig + 4) * 256 + nn] * W_SCALE);
        }
    for (int i = tid; i < 512; i += 512) sWfc1[i] = Wfc1[i] * INV_SQRT8_C;

    const int niter = N_EDGES / EPB;   // 10000

    auto bundle_issue = [&](int buf, int it_tgt) {
        if (it_tgt < niter) {
            const size_t e0 = (size_t)it_tgt * EPB;
            if (tid < 64) {
                cp_async16(smem_u32(sBas + buf * 256 + tid * 4), edge_basis + e0 * 8 + tid * 4);
            } else if (tid < 96) {
                cp_async16(smem_u32(sShs + buf * 128 + (tid - 64) * 4), edge_sh + e0 * 4 + (tid - 64) * 4);
            } else if (tid < 112) {
                cp_async16(smem_u32(sIdx + buf * 64 + (tid - 96) * 4), edge_idx + e0 * 2 + (tid - 96) * 4);
            }
        }
    };

    auto gather_issue = [&](int gbuf, int ibuf, bool valid) {
        if (valid) {
#pragma unroll
            for (int j = 0; j < 4; ++j) {
                const int c = tid + 512 * j;        // 0..2047
                const int row = c >> 6;              // edge 0..31
                const int off = (c & 63) * 4;
                const int src = sIdx[ibuf * 64 + 2 * row + 1];
                cp_async16(smem_u32(sGat + (gbuf * 32 + row) * GAT_STRIDE + off),
                           d_sv + (size_t)src * 256 + off);
            }
        }
    };

    // prologue: bundle(it0) -> wait -> gather(it0)
    bundle_issue(0, blockIdx.x);
    cp_commit();
    cp_wait<0>();
    __syncthreads();
    gather_issue(0, 0, blockIdx.x < niter);
    cp_commit();                        // pending: [gather(it0)]

    int li = 0;
    for (int it = blockIdx.x; it < niter; it += gridDim.x, ++li) {
        const int cur = li & 1;
        const int nit = it + gridDim.x;

        if (tid < 128) asm volatile("cp.async.bulk.wait_group 1;" ::: "memory");

        bundle_issue(cur ^ 1, nit);
        cp_commit();                    // pending: [gather(it), bundle(it+1)]

        // phase A: h for 32 edges (2048 values, 4 per thread)
#pragma unroll
        for (int i = tid; i < EPB * 64; i += 512) {
            const int el = i >> 6, k = i & 63;
            const float* bb = sBas + cur * 256 + el * 8;
            const float4 b0 = ld4s(bb);
            const float4 b1 = ld4s(bb + 4);
            float acc;
            acc = b0.x * sWfc1[0 * 64 + k];
            acc = fmaf(b0.y, sWfc1[1 * 64 + k], acc);
            acc = fmaf(b0.z, sWfc1[2 * 64 + k], acc);
            acc = fmaf(b0.w, sWfc1[3 * 64 + k], acc);
            acc = fmaf(b1.x, sWfc1[4 * 64 + k], acc);
            acc = fmaf(b1.y, sWfc1[5 * 64 + k], acc);
            acc = fmaf(b1.z, sWfc1[6 * 64 + k], acc);
            acc = fmaf(b1.w, sWfc1[7 * 64 + k], acc);
            const float t = __expf(-fabsf(acc));
            const float h = fmaxf(acc, 0.f) + log1p_poly(t) - LOG2_C;
            sHu[el * 68 + k] = f2tf32(h);
        }

        cp_wait<1>();                   // gather(it) landed
        __syncthreads();

        // phase B: tensor-core FC2 for this warp's 16-edge half
        float acc[4][4];
#pragma unroll
        for (int nb = 0; nb < 4; ++nb)
#pragma unroll
            for (int j = 0; j < 4; ++j) acc[nb][j] = 0.f;
#pragma unroll
        for (int ks = 0; ks < 8; ++ks) {
            const unsigned a0 = sHu[(qb + g    ) * 68 + ks * 8 + ctig    ];
            const unsigned a1 = sHu[(qb + g + 8) * 68 + ks * 8 + ctig    ];
            const unsigned a2 = sHu[(qb + g    ) * 68 + ks * 8 + ctig + 4];
            const unsigned a3 = sHu[(qb + g + 8) * 68 + ks * 8 + ctig + 4];
#pragma unroll
            for (int nb = 0; nb < 4; ++nb)
                mma_tf32(acc[nb][0], acc[nb][1], acc[nb][2], acc[nb][3],
                         a0, a1, a2, a3, bfrag[ks][nb][0], bfrag[ks][nb][1]);
        }

        // phase C: tensor product from gathered SMEM rows
        auto process = [&](float w, int q, int col) {
            const float* nrow = sGat + (cur * 32 + q) * GAT_STRIDE;
            const float4 sh = *reinterpret_cast<const float4*>(sShs + cur * 128 + 4 * q);
            float* st = sOut + (cur * EPB + q) * SOUT_STRIDE;
            if (region == 0) {
                st[col] = w * nrow[col] * sh.x;
            } else if (region == 1) {
                const int u = col - 64;
                const float b = w * nrow[u];
                st[128 + u] = b * sh.y;
                st[256 + u] = b * sh.z;
                st[384 + u] = b * sh.w;
            } else if (region == 2) {
                const int u = col - 128;
                const float ws = w * sh.x;
                st[128 + 64 + u] = ws * nrow[64 + 3 * u + 0];
                st[256 + 64 + u] = ws * nrow[64 + 3 * u + 1];
                st[384 + 64 + u] = ws * nrow[64 + 3 * u + 2];
            } else {
                const int u = col - 192;
                const float x0 = nrow[64 + 3 * u + 0];
                const float x1 = nrow[64 + 3 * u + 1];
                const float x2 = nrow[64 + 3 * u + 2];
                st[64 + u] = w * INV_SQRT3_C * (x0 * sh.y + x1 * sh.z + x2 * sh.w);
            }
        };
#pragma unroll
        for (int nb = 0; nb < 4; ++nb) {
            const int colb = n0 + nb * 8 + 2 * ctig;
            process(acc[nb][0], qb + g,     colb);
            process(acc[nb][1], qb + g,     colb + 1);
            process(acc[nb][2], qb + g + 8, colb);
            process(acc[nb][3], qb + g + 8, colb + 1);
        }

        cp_wait<0>();                   // bundle(it+1) landed
        __syncthreads();

        // 4x 512B bulk reduce-add per edge (32 edges -> tid<128)
        if (tid < 128) {
            asm volatile("fence.proxy.async.shared::cta;" ::: "memory");
            const int q = tid >> 2, part = tid & 3;
            const int dst = sIdx[cur * 64 + 2 * q];
            float* gp = (part == 0)
                      ? (d_cat_s + (size_t)dst * 640)
                      : (d_cat_v + ((size_t)dst * 3 + (part - 1)) * 640);
            const unsigned saddr = smem_u32(sOut + (cur * EPB + q) * SOUT_STRIDE + part * 128);
            asm volatile(
                "cp.reduce.async.bulk.global.shared::cta.bulk_group.add.f32 [%0], [%1], %2;"
                :: "l"(gp), "r"(saddr), "n"(512) : "memory");
            asm volatile("cp.async.bulk.commit_group;" ::: "memory");
        }

        gather_issue(cur ^ 1, cur ^ 1, nit < niter);
        cp_commit();                    // pending: [gather(it+1)]
    }
    if (tid < 128) asm volatile("cp.async.bulk.wait_group 0;" ::: "memory");
}

// ===========================================================================
// Unified tf32 tensor-core out-GEMM (unchanged)
// ===========================================================================
#define KCH 80
#define PAD 84
#define GEMM_SMEM (4 * 64 * PAD * 4)

__global__ void __launch_bounds__(256, 2)
out_gemm_tc(float* __restrict__ out)
{
    const int bid  = blockIdx.x;
    const int mode = (bid >= TILES_S);
    const int tile = mode ? bid - TILES_S : bid;
    const float* __restrict__ A  = mode ? d_cat_v   : d_cat_s;
    const float* __restrict__ Bt = mode ? d_WcatT_v : d_WcatT_s;

    extern __shared__ float sm[];
    float* sA = sm;
    float* sB = sm + 2 * 64 * PAD;

    const int tid = threadIdx.x;
    const int lane = tid & 31, warp = tid >> 5;
    const int g = lane >> 2, ctig = lane & 3;
    const int m0 = (warp & 3) * 16;
    const int n0 = (warp >> 2) * 32;
    const int r0 = tile * 64;

    auto stage = [&](int buf, int c) {
        const int k0 = c * KCH;
        float* sAb = sA + buf * 64 * PAD;
        float* sBb = sB + buf * 64 * PAD;
#pragma unroll
        for (int j = 0; j < 5; ++j) {
            const int idx = tid + 256 * j;
            const int row = idx / 20, u = idx - row * 20;
            cp_async16(smem_u32(sAb + row * PAD + 4 * u),
                       A + (size_t)(r0 + row) * 640 + k0 + 4 * u);
            cp_async16(smem_u32(sBb + row * PAD + 4 * u),
                       Bt + (size_t)row * 640 + k0 + 4 * u);
        }
        cp_commit();
    };

    float acc[4][4];
#pragma unroll
    for (int nb = 0; nb < 4; ++nb)
#pragma unroll
        for (int j = 0; j < 4; ++j) acc[nb][j] = 0.f;

    stage(0, 0);

#pragma unroll 1
    for (int c = 0; c < 8; ++c) {
        if (c < 7) { stage((c + 1) & 1, c + 1); cp_wait<1>(); }
        else       { cp_wait<0>(); }
        __syncthreads();

        const float* pa = sA + (c & 1) * 64 * PAD + m0 * PAD;
        const float* pb = sB + (c & 1) * 64 * PAD + n0 * PAD;
#pragma unroll
        for (int ks = 0; ks < KCH / 8; ++ks) {
            const int kb = ks * 8;
            const unsigned a0 = f2tf32(pa[ g      * PAD + kb + ctig    ]);
            const unsigned a1 = f2tf32(pa[(g + 8) * PAD + kb + ctig    ]);
            const unsigned a2 = f2tf32(pa[ g      * PAD + kb + ctig + 4]);
            const unsigned a3 = f2tf32(pa[(g + 8) * PAD + kb + ctig + 4]);
#pragma unroll
            for (int nb = 0; nb < 4; ++nb) {
                const unsigned b0 = __float_as_uint(pb[(nb * 8 + g) * PAD + kb + ctig    ]);
                const unsigned b1 = __float_as_uint(pb[(nb * 8 + g) * PAD + kb + ctig + 4]);
                mma_tf32(acc[nb][0], acc[nb][1], acc[nb][2], acc[nb][3],
                         a0, a1, a2, a3, b0, b1);
            }
        }
        __syncthreads();
    }

#pragma unroll
    for (int nb = 0; nb < 4; ++nb) {
        const int col = n0 + nb * 8 + 2 * ctig;
        const int row1 = r0 + m0 + g;
        const int row2 = row1 + 8;
        if (mode == 0) {
            if (row1 < N_NODES)
                *reinterpret_cast<float2*>(out + (size_t)row1 * 256 + col) =
                    make_float2(acc[nb][0], acc[nb][1]);
            if (row2 < N_NODES)
                *reinterpret_cast<float2*>(out + (size_t)row2 * 256 + col) =
                    make_float2(acc[nb][2], acc[nb][3]);
        } else {
            if (row1 < 3 * N_NODES) {
                const int n = row1 / 3, cc = row1 - 3 * (row1 / 3);
                float* o = out + (size_t)n * 256 + 64 + cc;
                o[3 * col] = acc[nb][0];
                o[3 * (col + 1)] = acc[nb][1];
            }
            if (row2 < 3 * N_NODES) {
                const int n = row2 / 3, cc = row2 - 3 * (row2 / 3);
                float* o = out + (size_t)n * 256 + 64 + cc;
                o[3 * col] = acc[nb][2];
                o[3 * (col + 1)] = acc[nb][3];
            }
        }
    }
}

// ---------------------------------------------------------------------------
extern "C" void kernel_launch(void* const* d_in, const int* /*in_sizes*/, int /*n_in*/,
                              void* d_out, int /*out_size*/)
{
    const float* node_feat  = (const float*)d_in[0];
    const float* node_attr  = (const float*)d_in[1];
    const float* edge_sh    = (const float*)d_in[2];
    const float* edge_basis = (const float*)d_in[3];
    const float* W1s        = (const float*)d_in[4];
    const float* W1v        = (const float*)d_in[5];
    const float* Wfc1       = (const float*)d_in[6];
    const float* Wfc2       = (const float*)d_in[7];
    const float* W2s        = (const float*)d_in[8];
    const float* W2v        = (const float*)d_in[9];
    const float* Wsc_s      = (const float*)d_in[10];
    const float* Wsc_v      = (const float*)d_in[11];
    const int*   edge_idx   = (const int*)d_in[12];
    float* out = (float*)d_out;

    cudaFuncSetAttribute(edge_kernel, cudaFuncAttributeMaxDynamicSharedMemorySize, EDGE_SMEM);
    cudaFuncSetAttribute(out_gemm_tc, cudaFuncAttributeMaxDynamicSharedMemorySize, GEMM_SMEM);

    wfold_kernel<<<160, 256>>>(W2s, Wsc_s, W2v, Wsc_v);
    nodeprep_kernel<<<296, 256>>>(node_feat, node_attr, W1s, W1v);
    edge_kernel<<<148, 512, EDGE_SMEM>>>(edge_sh, edge_basis, Wfc1, Wfc2, edge_idx);

    out_gemm_tc<<<TILES_S + TILES_V, 256, GEMM_SMEM>>>(out);
}

// round 17
// speedup vs baseline: 1.1826x; 1.1826x over previous
#include <cuda_runtime.h>
#include <cstdint>
#include <cstddef>

#define N_NODES 20000
#define N_EDGES 320000
#define EPB 16

#define LOG2_C       0.6931471805599453f
#define INV_SQRT3_C  0.5773502691896258f
#define INV_SQRT8_C  0.35355339059327373f
#define W_SCALE      0.125f
#define INV_MUL_C    0.125f
#define SC_A_C       0.02209708691207961f   // 1/sqrt(128) * 1/sqrt(16)
#define SC_B_C       0.04419417382415922f   // 1/sqrt(512)

#define ROWS_S 20032
#define ROWS_V 60032
#define TILES_S 313
#define TILES_V 938

// scratch (__device__ globals). Device-code references only; host uses
// cudaGetSymbolAddress (supported) for the memsets.
__device__ __align__(1024) float d_sv[(size_t)N_NODES * 256];
__device__ __align__(1024) float d_agg_s[(size_t)ROWS_S * 128];
__device__ __align__(1024) float d_agg_v[(size_t)ROWS_V * 128];
__device__ __align__(1024) float d_WcatT_s[64 * 640];   // n-major, k-permuted, tf32 bits
__device__ __align__(1024) float d_WcatT_v[64 * 640];

__device__ __forceinline__ unsigned smem_u32(const void* p) {
    return (unsigned)__cvta_generic_to_shared(p);
}
__device__ __forceinline__ float4 ld4s(const float* p) {
    return *reinterpret_cast<const float4*>(p);
}
__device__ __forceinline__ void cp_async16(unsigned saddr, const void* gaddr) {
    asm volatile("cp.async.cg.shared.global [%0], [%1], 16;" :: "r"(saddr), "l"(gaddr));
}
__device__ __forceinline__ void cp_async4(unsigned saddr, const void* gaddr) {
    asm volatile("cp.async.ca.shared.global [%0], [%1], 4;" :: "r"(saddr), "l"(gaddr));
}
__device__ __forceinline__ void cp_commit() {
    asm volatile("cp.async.commit_group;" ::: "memory");
}
template<int NWAIT>
__device__ __forceinline__ void cp_wait() {
    asm volatile("cp.async.wait_group %0;" :: "n"(NWAIT) : "memory");
}

// ---- tf32 helpers ------------------------------------------------------
__device__ __forceinline__ unsigned f2tf32(float f) {
    unsigned r;
    asm("cvt.rna.tf32.f32 %0, %1;" : "=r"(r) : "f"(f));
    return r;
}
__device__ __forceinline__ void mma_tf32(float& c0, float& c1, float& c2, float& c3,
                                         unsigned a0, unsigned a1, unsigned a2, unsigned a3,
                                         unsigned b0, unsigned b1) {
    asm volatile(
        "mma.sync.aligned.m16n8k8.row.col.f32.tf32.tf32.f32 "
        "{%0,%1,%2,%3}, {%4,%5,%6,%7}, {%8,%9}, {%0,%1,%2,%3};"
        : "+f"(c0), "+f"(c1), "+f"(c2), "+f"(c3)
        : "r"(a0), "r"(a1), "r"(a2), "r"(a3), "r"(b0), "r"(b1));
}

// ---- log1p(t), t in [0,1]: degree-7 poly (err ~2e-7) --------------------
__device__ __forceinline__ float log1p_poly(float t) {
    const float u = fmaf(2.f, t, -1.f);
    float p = 0.0000800429f;
    p = fmaf(p, u, -0.000272121f);
    p = fmaf(p, u,  0.000811464f);
    p = fmaf(p, u, -0.00305802f);
    p = fmaf(p, u,  0.01234897f);
    p = fmaf(p, u, -0.05556137f);
    p = fmaf(p, u,  0.33333319f);
    p = fmaf(p, u,  0.4054653f);
    return p;
}

// ---------------------------------------------------------------------------
// wfold: WcatT[n][k'] with PERMUTED k: k' in [0,512) -> Wsc (T part),
// k' in [512,640) -> W2 (agg part). Scales folded, tf32 bits.
// ---------------------------------------------------------------------------
__global__ void wfold_kernel(const float* __restrict__ W2s, const float* __restrict__ Wsc_s,
                             const float* __restrict__ W2v, const float* __restrict__ Wsc_v)
{
    const int i = blockIdx.x * blockDim.x + threadIdx.x;
    if (i >= 40960) return;
    const int n = i / 640, k = i - n * 640;
    const float vs = (k < 512) ? Wsc_s[k * 64 + n] * SC_B_C : W2s[(k - 512) * 64 + n] * SC_A_C;
    const float vv = (k < 512) ? Wsc_v[k * 64 + n] * SC_B_C : W2v[(k - 512) * 64 + n] * SC_A_C;
    d_WcatT_s[i] = __uint_as_float(f2tf32(vs));
    d_WcatT_v[i] = __uint_as_float(f2tf32(vv));
}

// ---------------------------------------------------------------------------
// node prep: ONLY d_sv = [s0@W1s | v0@W1v] * 1/8 (T parts now fused into gemm)
// ---------------------------------------------------------------------------
__global__ void __launch_bounds__(256)
nodeprep_kernel(const float* __restrict__ node_feat,
                const float* __restrict__ W1s,
                const float* __restrict__ W1v)
{
    __shared__ float sW1s[4096];
    __shared__ float sW1v[4096];
    __shared__ float sNF[4][256];

    const int tid = threadIdx.x;
    for (int i = tid; i < 4096; i += 256) { sW1s[i] = W1s[i]; sW1v[i] = W1v[i]; }
    __syncthreads();

    const int ngroups = N_NODES / 4;
    for (int g = blockIdx.x; g < ngroups; g += gridDim.x) {
        const int n0 = g * 4;
        __syncthreads();
        for (int i = tid; i < 1024; i += 256) {
            const int nl = i >> 8, j = i & 255;
            sNF[nl][j] = node_feat[(size_t)(n0 + nl) * 256 + j];
        }
        __syncthreads();
        const int nl = tid >> 6, w = tid & 63;
        const int n = n0 + nl;
        float sacc = 0.f, v0a = 0.f, v1a = 0.f, v2a = 0.f;
#pragma unroll
        for (int u = 0; u < 64; ++u) {
            const float ws = sW1s[u * 64 + w];
            const float wvv = sW1v[u * 64 + w];
            sacc = fmaf(sNF[nl][u], ws, sacc);
            v0a  = fmaf(sNF[nl][64 + 3 * u + 0], wvv, v0a);
            v1a  = fmaf(sNF[nl][64 + 3 * u + 1], wvv, v1a);
            v2a  = fmaf(sNF[nl][64 + 3 * u + 2], wvv, v2a);
        }
        float* o = d_sv + (size_t)n * 256;
        o[w] = sacc * INV_MUL_C;
        o[64 + 3 * w + 0] = v0a * INV_MUL_C;
        o[64 + 3 * w + 1] = v1a * INV_MUL_C;
        o[64 + 3 * w + 2] = v2a * INV_MUL_C;
    }
}

// ---------------------------------------------------------------------------
// edge kernel (R14-proven config): EPB=16, 256 thr, 2 CTA/SM, gather prefetch.
// Reduce targets are now the compact d_agg_s / d_agg_v (128-float rows).
// ---------------------------------------------------------------------------
#define SOUT_STRIDE 516
#define GAT_STRIDE 260
#define EDGE_SMEM (26880 * 4)

__global__ void __launch_bounds__(256, 2)
edge_kernel(const float* __restrict__ edge_sh,
            const float* __restrict__ edge_basis,
            const float* __restrict__ Wfc1,
            const float* __restrict__ Wfc2,
            const int*   __restrict__ edge_idx)
{
    extern __shared__ float esm[];
    float*    sOut  = esm;
    float*    sGat  = esm + 16512;
    float*    sH    = esm + 24832;
    unsigned* sHu   = reinterpret_cast<unsigned*>(sH);
    float*    sWfc1 = esm + 25920;
    float*    sBas  = esm + 26432;
    float*    sShs  = esm + 26688;
    int*      sIdx  = (int*)(esm + 26816);

    const int tid  = threadIdx.x;
    const int lane = tid & 31, warp = tid >> 5;
    const int g    = lane >> 2;
    const int ctig = lane & 3;
    const int n0   = warp * 32;
    const int region = warp >> 1;

    unsigned bfrag[8][4][2];
#pragma unroll
    for (int ks = 0; ks < 8; ++ks)
#pragma unroll
        for (int nb = 0; nb < 4; ++nb) {
            const int nn = n0 + nb * 8 + g;
            bfrag[ks][nb][0] = f2tf32(Wfc2[(ks * 8 + ctig    ) * 256 + nn] * W_SCALE);
            bfrag[ks][nb][1] = f2tf32(Wfc2[(ks * 8 + ctig + 4) * 256 + nn] * W_SCALE);
        }
    for (int i = tid; i < 512; i += 256) sWfc1[i] = Wfc1[i] * INV_SQRT8_C;

    const int niter = N_EDGES / EPB;

    auto prefetch = [&](int buf, int it_tgt) {
        const size_t e0 = (size_t)it_tgt * EPB;
        if (tid < 32) {
            cp_async16(smem_u32(sBas + buf * 128 + tid * 4), edge_basis + e0 * 8 + tid * 4);
        } else if (tid < 48) {
            cp_async16(smem_u32(sShs + buf * 64 + (tid - 32) * 4), edge_sh + e0 * 4 + (tid - 32) * 4);
        } else if (tid < 56) {
            cp_async16(smem_u32(sIdx + buf * 32 + (tid - 48) * 4), edge_idx + e0 * 2 + (tid - 48) * 4);
        }
    };

    auto gather_issue = [&](int gbuf, int ibuf, bool valid) {
        if (valid) {
#pragma unroll
            for (int j = 0; j < 4; ++j) {
                const int c = tid + 256 * j;
                const int row = c >> 6;
                const int off = (c & 63) * 4;
                const int src = sIdx[ibuf * 32 + 2 * row + 1];
                cp_async16(smem_u32(sGat + (gbuf * 16 + row) * GAT_STRIDE + off),
                           d_sv + (size_t)src * 256 + off);
            }
        }
    };

    if (tid < 56) { prefetch(0, blockIdx.x); cp_commit(); cp_wait<0>(); }
    __syncthreads();
    gather_issue(0, 0, blockIdx.x < niter);
    cp_commit();                        // pending: [gather(it0)]

    int li = 0;
    for (int it = blockIdx.x; it < niter; it += gridDim.x, ++li) {
        const int cur = li & 1;
        const int nit = it + gridDim.x;

        if (tid < 4 * EPB) asm volatile("cp.async.bulk.wait_group 1;" ::: "memory");

        if (tid < 56) {
            if (nit < niter) prefetch(cur ^ 1, nit);
        }
        cp_commit();                    // pending: [gather(it), bundle(it+1)]

        // phase A
#pragma unroll
        for (int i = tid; i < EPB * 64; i += 256) {
            const int el = i >> 6, k = i & 63;
            const float* bb = sBas + cur * 128 + el * 8;
            const float4 b0 = ld4s(bb);
            const float4 b1 = ld4s(bb + 4);
            float acc;
            acc = b0.x * sWfc1[0 * 64 + k];
            acc = fmaf(b0.y, sWfc1[1 * 64 + k], acc);
            acc = fmaf(b0.z, sWfc1[2 * 64 + k], acc);
            acc = fmaf(b0.w, sWfc1[3 * 64 + k], acc);
            acc = fmaf(b1.x, sWfc1[4 * 64 + k], acc);
            acc = fmaf(b1.y, sWfc1[5 * 64 + k], acc);
            acc = fmaf(b1.z, sWfc1[6 * 64 + k], acc);
            acc = fmaf(b1.w, sWfc1[7 * 64 + k], acc);
            const float t = __expf(-fabsf(acc));
            const float h = fmaxf(acc, 0.f) + log1p_poly(t) - LOG2_C;
            sHu[el * 68 + k] = f2tf32(h);
        }

        cp_wait<1>();                   // gather(it) landed
        __syncthreads();

        // phase B
        float acc[4][4];
#pragma unroll
        for (int nb = 0; nb < 4; ++nb)
#pragma unroll
            for (int j = 0; j < 4; ++j) acc[nb][j] = 0.f;
#pragma unroll
        for (int ks = 0; ks < 8; ++ks) {
            const unsigned a0 = sHu[ g      * 68 + ks * 8 + ctig    ];
            const unsigned a1 = sHu[(g + 8) * 68 + ks * 8 + ctig    ];
            const unsigned a2 = sHu[ g      * 68 + ks * 8 + ctig + 4];
            const unsigned a3 = sHu[(g + 8) * 68 + ks * 8 + ctig + 4];
#pragma unroll
            for (int nb = 0; nb < 4; ++nb)
                mma_tf32(acc[nb][0], acc[nb][1], acc[nb][2], acc[nb][3],
                         a0, a1, a2, a3, bfrag[ks][nb][0], bfrag[ks][nb][1]);
        }

        // phase C
        auto process = [&](float w, int q, int col) {
            const float* nrow = sGat + (cur * 16 + q) * GAT_STRIDE;
            const float4 sh = *reinterpret_cast<const float4*>(sShs + cur * 64 + 4 * q);
            float* st = sOut + (cur * EPB + q) * SOUT_STRIDE;
            if (region == 0) {
                st[col] = w * nrow[col] * sh.x;
            } else if (region == 1) {
                const int u = col - 64;
                const float b = w * nrow[u];
                st[128 + u] = b * sh.y;
                st[256 + u] = b * sh.z;
                st[384 + u] = b * sh.w;
            } else if (region == 2) {
                const int u = col - 128;
                const float ws = w * sh.x;
                st[128 + 64 + u] = ws * nrow[64 + 3 * u + 0];
                st[256 + 64 + u] = ws * nrow[64 + 3 * u + 1];
                st[384 + 64 + u] = ws * nrow[64 + 3 * u + 2];
            } else {
                const int u = col - 192;
                const float x0 = nrow[64 + 3 * u + 0];
                const float x1 = nrow[64 + 3 * u + 1];
                const float x2 = nrow[64 + 3 * u + 2];
                st[64 + u] = w * INV_SQRT3_C * (x0 * sh.y + x1 * sh.z + x2 * sh.w);
            }
        };
#pragma unroll
        for (int nb = 0; nb < 4; ++nb) {
            const int colb = n0 + nb * 8 + 2 * ctig;
            process(acc[nb][0], g,     colb);
            process(acc[nb][1], g,     colb + 1);
            process(acc[nb][2], g + 8, colb);
            process(acc[nb][3], g + 8, colb + 1);
        }

        cp_wait<0>();                   // bundle(it+1) landed
        __syncthreads();

        if (tid < 4 * EPB) {
            asm volatile("fence.proxy.async.shared::cta;" ::: "memory");
            const int q = tid >> 2, part = tid & 3;
            const int dst = sIdx[cur * 32 + 2 * q];
            float* gp = (part == 0)
                      ? (d_agg_s + (size_t)dst * 128)
                      : (d_agg_v + ((size_t)dst * 3 + (part - 1)) * 128);
            const unsigned saddr = smem_u32(sOut + (cur * EPB + q) * SOUT_STRIDE + part * 128);
            asm volatile(
                "cp.reduce.async.bulk.global.shared::cta.bulk_group.add.f32 [%0], [%1], %2;"
                :: "l"(gp), "r"(saddr), "n"(512) : "memory");
            asm volatile("cp.async.bulk.commit_group;" ::: "memory");
        }

        gather_issue(cur ^ 1, cur ^ 1, nit < niter);
        cp_commit();                    // pending: [gather(it+1)]
    }
    if (tid < 4 * EPB) asm volatile("cp.async.bulk.wait_group 0;" ::: "memory");
}

// ===========================================================================
// Fused tf32 out-GEMM: k' permuted (T first). Chunks 0-7 (k'<512): A
// fragments computed on the fly from feat (x) attr; chunks 8-9: agg via
// cp.async. B always via cp.async from WcatT.
// smem: sB[2][64*68] + sAgg[2][64*68] + sFeat[2][64*12] + sAttr[512]
//     = 19456 floats = 77824 B -> 2 CTAs/SM.
// ===========================================================================
#define PB2 68
#define PF 12
#define GEMM_SMEM (19456 * 4)

__global__ void __launch_bounds__(256, 2)
out_gemm_tc(const float* __restrict__ node_feat,
            const float* __restrict__ node_attr,
            float* __restrict__ out)
{
    const int bid  = blockIdx.x;
    const int mode = (bid >= TILES_S);
    const int tile = mode ? bid - TILES_S : bid;
    const float* __restrict__ Agg = mode ? d_agg_v   : d_agg_s;
    const float* __restrict__ Bt  = mode ? d_WcatT_v : d_WcatT_s;

    extern __shared__ float sm[];
    float* sB    = sm;                           // [2][64*68]
    float* sAgg  = sm + 2 * 64 * PB2;            // [2][64*68]
    float* sFeat = sm + 4 * 64 * PB2;            // [2][64*12]
    float* sAttr = sm + 4 * 64 * PB2 + 2 * 64 * PF;  // [64*8]

    const int tid = threadIdx.x;
    const int lane = tid & 31, warp = tid >> 5;
    const int g = lane >> 2, ctig = lane & 3;
    const int m0 = (warp & 3) * 16;
    const int n0 = (warp >> 2) * 32;
    const int r0 = tile * 64;

    // attr tile (once per tile)
    for (int i = tid; i < 512; i += 256) {
        const int row = i >> 3, j = i & 7;
        const int grow = r0 + row;
        int n = mode ? grow / 3 : grow;
        if (n >= N_NODES) n = 0;
        sAttr[row * 8 + j] = node_attr[(size_t)n * 8 + j];
    }

    auto stage = [&](int c) {
        const int buf = c & 1;
        float* sBb = sB + buf * 64 * PB2;
#pragma unroll
        for (int j = 0; j < 4; ++j) {
            const int idx = tid + 256 * j;
            const int row = idx >> 4, u = idx & 15;
            cp_async16(smem_u32(sBb + row * PB2 + u * 4),
                       Bt + (size_t)row * 640 + c * 64 + u * 4);
        }
        if (c < 8) {
            float* sFb = sFeat + buf * 64 * PF;
            if (mode == 0) {
                if (tid < 128) {
                    const int row = tid >> 1, u = tid & 1;
                    int grow = r0 + row; if (grow >= N_NODES) grow = 0;
                    cp_async16(smem_u32(sFb + row * PF + u * 4),
                               node_feat + (size_t)grow * 256 + c * 8 + u * 4);
                }
            } else {
#pragma unroll
                for (int j = 0; j < 2; ++j) {
                    const int idx = tid + 256 * j;
                    const int row = idx >> 3, jj = idx & 7;
                    const int grow = r0 + row;
                    int n = grow / 3, cc = grow - 3 * n;
                    if (n >= N_NODES) { n = 0; cc = 0; }
                    cp_async4(smem_u32(sFb + row * PF + jj),
                              node_feat + (size_t)n * 256 + 64 + 3 * (c * 8 + jj) + cc);
                }
            }
        } else {
            float* sAb = sAgg + buf * 64 * PB2;
#pragma unroll
            for (int j = 0; j < 4; ++j) {
                const int idx = tid + 256 * j;
                const int row = idx >> 4, u = idx & 15;
                cp_async16(smem_u32(sAb + row * PB2 + u * 4),
                           Agg + (size_t)(r0 + row) * 128 + (c - 8) * 64 + u * 4);
            }
        }
        cp_commit();
    };

    float acc[4][4];
#pragma unroll
    for (int nb = 0; nb < 4; ++nb)
#pragma unroll
        for (int j = 0; j < 4; ++j) acc[nb][j] = 0.f;

    __syncthreads();    // sAttr visible
    const float at00 = sAttr[(m0 + g    ) * 8 + ctig];
    const float at01 = sAttr[(m0 + g    ) * 8 + ctig + 4];
    const float at10 = sAttr[(m0 + g + 8) * 8 + ctig];
    const float at11 = sAttr[(m0 + g + 8) * 8 + ctig + 4];

    stage(0);

#pragma unroll 1
    for (int c = 0; c < 10; ++c) {
        if (c < 9) { stage(c + 1); cp_wait<1>(); }
        else       { cp_wait<0>(); }
        __syncthreads();

        const int buf = c & 1;
        const float* pb = sB + buf * 64 * PB2 + n0 * PB2;
        if (c < 8) {
            const float* f0p = sFeat + buf * 64 * PF + (m0 + g) * PF;
            const float* f1p = f0p + 8 * PF;
#pragma unroll
            for (int ks = 0; ks < 8; ++ks) {
                const float f0 = f0p[ks], f1 = f1p[ks];
                const unsigned a0 = f2tf32(f0 * at00);
                const unsigned a1 = f2tf32(f1 * at10);
                const unsigned a2 = f2tf32(f0 * at01);
                const unsigned a3 = f2tf32(f1 * at11);
                const int kb = ks * 8;
#pragma unroll
                for (int nb = 0; nb < 4; ++nb) {
                    const unsigned b0 = __float_as_uint(pb[(nb * 8 + g) * PB2 + kb + ctig    ]);
                    const unsigned b1 = __float_as_uint(pb[(nb * 8 + g) * PB2 + kb + ctig + 4]);
                    mma_tf32(acc[nb][0], acc[nb][1], acc[nb][2], acc[nb][3],
                             a0, a1, a2, a3, b0, b1);
                }
            }
        } else {
            const float* pa = sAgg + buf * 64 * PB2 + m0 * PB2;
#pragma unroll
            for (int ks = 0; ks < 8; ++ks) {
                const int kb = ks * 8;
                const unsigned a0 = f2tf32(pa[ g      * PB2 + kb + ctig    ]);
                const unsigned a1 = f2tf32(pa[(g + 8) * PB2 + kb + ctig    ]);
                const unsigned a2 = f2tf32(pa[ g      * PB2 + kb + ctig + 4]);
                const unsigned a3 = f2tf32(pa[(g + 8) * PB2 + kb + ctig + 4]);
#pragma unroll
                for (int nb = 0; nb < 4; ++nb) {
                    const unsigned b0 = __float_as_uint(pb[(nb * 8 + g) * PB2 + kb + ctig    ]);
                    const unsigned b1 = __float_as_uint(pb[(nb * 8 + g) * PB2 + kb + ctig + 4]);
                    mma_tf32(acc[nb][0], acc[nb][1], acc[nb][2], acc[nb][3],
                             a0, a1, a2, a3, b0, b1);
                }
            }
        }
        __syncthreads();
    }

#pragma unroll
    for (int nb = 0; nb < 4; ++nb) {
        const int col = n0 + nb * 8 + 2 * ctig;
        const int row1 = r0 + m0 + g;
        const int row2 = row1 + 8;
        if (mode == 0) {
            if (row1 < N_NODES)
                *reinterpret_cast<float2*>(out + (size_t)row1 * 256 + col) =
                    make_float2(acc[nb][0], acc[nb][1]);
            if (row2 < N_NODES)
                *reinterpret_cast<float2*>(out + (size_t)row2 * 256 + col) =
                    make_float2(acc[nb][2], acc[nb][3]);
        } else {
            if (row1 < 3 * N_NODES) {
                const int n = row1 / 3, cc = row1 - 3 * (row1 / 3);
                float* o = out + (size_t)n * 256 + 64 + cc;
                o[3 * col] = acc[nb][0];
                o[3 * (col + 1)] = acc[nb][1];
            }
            if (row2 < 3 * N_NODES) {
                const int n = row2 / 3, cc = row2 - 3 * (row2 / 3);
                float* o = out + (size_t)n * 256 + 64 + cc;
                o[3 * col] = acc[nb][2];
                o[3 * (col + 1)] = acc[nb][3];
            }
        }
    }
}

// ---------------------------------------------------------------------------
extern "C" void kernel_launch(void* const* d_in, const int* /*in_sizes*/, int /*n_in*/,
                              void* d_out, int /*out_size*/)
{
    const float* node_feat  = (const float*)d_in[0];
    const float* node_attr  = (const float*)d_in[1];
    const float* edge_sh    = (const float*)d_in[2];
    const float* edge_basis = (const float*)d_in[3];
    const float* W1s        = (const float*)d_in[4];
    const float* W1v        = (const float*)d_in[5];
    const float* Wfc1       = (const float*)d_in[6];
    const float* Wfc2       = (const float*)d_in[7];
    const float* W2s        = (const float*)d_in[8];
    const float* W2v        = (const float*)d_in[9];
    const float* Wsc_s      = (const float*)d_in[10];
    const float* Wsc_v      = (const float*)d_in[11];
    const int*   edge_idx   = (const int*)d_in[12];
    float* out = (float*)d_out;

    cudaFuncSetAttribute(edge_kernel, cudaFuncAttributeMaxDynamicSharedMemorySize, EDGE_SMEM);
    cudaFuncSetAttribute(out_gemm_tc, cudaFuncAttributeMaxDynamicSharedMemorySize, GEMM_SMEM);

    // zero agg buffers (graph-capturable async memsets; symbol address query
    // is the supported host-side way to reference __device__ globals)
    void* agg_s_ptr = nullptr;
    void* agg_v_ptr = nullptr;
    cudaGetSymbolAddress(&agg_s_ptr, d_agg_s);
    cudaGetSymbolAddress(&agg_v_ptr, d_agg_v);
    cudaMemsetAsync(agg_s_ptr, 0, sizeof(float) * (size_t)ROWS_S * 128);
    cudaMemsetAsync(agg_v_ptr, 0, sizeof(float) * (size_t)ROWS_V * 128);

    wfold_kernel<<<160, 256>>>(W2s, Wsc_s, W2v, Wsc_v);
    nodeprep_kernel<<<296, 256>>>(node_feat, W1s, W1v);
    edge_kernel<<<296, 256, EDGE_SMEM>>>(edge_sh, edge_basis, Wfc1, Wfc2, edge_idx);

    out_gemm_tc<<<TILES_S + TILES_V, 256, GEMM_SMEM>>>(node_feat, node_attr, out);
}